// round 6
// baseline (speedup 1.0000x reference)
#include <cuda_runtime.h>
#include <math.h>

#define BB 32
#define NN 64
#define KK 128
#define NPAIR (BB*NN*NN)   // 131072
#define NNODE (BB*NN)      // 2048

// ---------------- scratch (no cudaMalloc allowed) ----------------
__device__ float g_rad[NPAIR*8];
__device__ float g_Y[NPAIR*8];
__device__ float g_mask[NPAIR];
__device__ float g_h1[NNODE*KK];
__device__ float g_s1[NNODE*KK];
__device__ float g_v1[NNODE*3*KK];
__device__ float g_s2[NNODE*KK];

__device__ __forceinline__ float siluf(float x) { return x / (1.0f + __expf(-x)); }

typedef unsigned long long u64;
__device__ __forceinline__ u64 pk2(float lo, float hi) {
    u64 r; asm("mov.b64 %0, {%1,%2};" : "=l"(r) : "f"(lo), "f"(hi)); return r;
}
__device__ __forceinline__ void fma2(u64& a, u64 x, u64 y) {
    asm("fma.rn.f32x2 %0, %1, %2, %3;" : "=l"(a) : "l"(x), "l"(y), "l"(a));
}
__device__ __forceinline__ float2 upk(u64 v) {
    float2 o; asm("mov.b64 {%0,%1}, %2;" : "=f"(o.x), "=f"(o.y) : "l"(v)); return o;
}

// ---------------- kernel 1: pairwise geometry ----------------
__global__ void k_geom(const float* __restrict__ frac, const float* __restrict__ cell)
{
    int idx = blockIdx.x * blockDim.x + threadIdx.x;
    if (idx >= NPAIR) return;
    int b = idx >> 12;
    int i = (idx >> 6) & 63;
    int j = idx & 63;
    const float* fi = frac + (b*NN + i)*3;
    const float* fj = frac + (b*NN + j)*3;
    float d0 = fi[0]-fj[0], d1 = fi[1]-fj[1], d2 = fi[2]-fj[2];
    d0 -= rintf(d0); d1 -= rintf(d1); d2 -= rintf(d2);
    const float* C = cell + b*9;
    float x = d0*C[0] + d1*C[3] + d2*C[6];
    float y = d0*C[1] + d1*C[4] + d2*C[7];
    float z = d0*C[2] + d1*C[5] + d2*C[8];
    float r2 = fmaxf(x*x + y*y + z*z, 1e-12f);
    float r = sqrtf(r2);
    bool m = (r < 5.0f) && (i != j);
    float mf = m ? 1.0f : 0.0f;
    float rs = m ? r : 1.0f;
    float inv = 1.0f / rs;
    float ux = x*inv*mf, uy = y*inv*mf, uz = z*inv*mf;
    float u = rs * 0.2f;
    float u2 = u*u, u4 = u2*u2, u5 = u4*u;
    float fc = 1.0f - 21.0f*u5 + 35.0f*u5*u - 15.0f*u5*u2;
    fc = (u < 1.0f) ? fc : 0.0f;
    float pref = 0.6324555320336759f * inv * fc * mf;
    float w = 0.6283185307179586f * rs;
    float* rp = g_rad + (size_t)idx*8;
    #pragma unroll
    for (int n = 1; n <= 8; ++n) rp[n-1] = pref * sinf((float)n * w);
    const float s3 = 1.7320508075688772f, s5 = 2.23606797749979f, s15 = 3.872983346207417f;
    float* Y = g_Y + (size_t)idx*8;
    Y[0] = s3*ux; Y[1] = s3*uy; Y[2] = s3*uz;
    Y[3] = s15*ux*uy;
    Y[4] = s15*uy*uz;
    Y[5] = 0.5f*s5*(3.0f*uz*uz - 1.0f);
    Y[6] = s15*ux*uz;
    Y[7] = 0.5f*s15*(ux*ux - uy*uy);
    g_mask[idx] = mf;
}

// ---------------- 64-wide dense layer, 256 threads, FFMA2 ----------------
// In: [64][CDIM] smem, W: [CDIM][64] smem, Out: [64][OSTR] smem (silu applied)
template<int CDIM>
__device__ __forceinline__ void dl256(const float* __restrict__ In,
                                      const float* __restrict__ W,
                                      const float* __restrict__ bias,
                                      float* __restrict__ Out, int t, int ostr)
{
    int j = t >> 2;
    int h0 = (t & 3) * 16;
    u64 acc[8];
    #pragma unroll
    for (int i = 0; i < 8; ++i) acc[i] = pk2(bias[h0+2*i], bias[h0+2*i+1]);
    #pragma unroll 1
    for (int c = 0; c < CDIM; c += 4) {
        float4 iv = *(const float4*)(In + j*CDIM + c);
        float a4[4] = {iv.x, iv.y, iv.z, iv.w};
        #pragma unroll
        for (int d = 0; d < 4; ++d) {
            u64 ap = pk2(a4[d], a4[d]);
            const longlong2* wr = (const longlong2*)(W + (c+d)*64 + h0);
            longlong2 q0 = wr[0], q1 = wr[1], q2 = wr[2], q3 = wr[3];
            fma2(acc[0], ap, (u64)q0.x); fma2(acc[1], ap, (u64)q0.y);
            fma2(acc[2], ap, (u64)q1.x); fma2(acc[3], ap, (u64)q1.y);
            fma2(acc[4], ap, (u64)q2.x); fma2(acc[5], ap, (u64)q2.y);
            fma2(acc[6], ap, (u64)q3.x); fma2(acc[7], ap, (u64)q3.y);
        }
    }
    #pragma unroll
    for (int i = 0; i < 8; i += 2) {
        float2 p0 = upk(acc[i]), p1 = upk(acc[i+1]);
        float4 o; o.x = siluf(p0.x); o.y = siluf(p0.y); o.z = siluf(p1.x); o.w = siluf(p1.y);
        *(float4*)(Out + j*ostr + h0 + 2*i) = o;
    }
}

// ---------------- kernel 2: phase 1 (256 threads) ----------------
__global__ void __launch_bounds__(256) k_phase1(
    const float* __restrict__ w_embed,
    const float* __restrict__ r1_w0, const float* __restrict__ r1_b0,
    const float* __restrict__ r1_w1, const float* __restrict__ r1_b1,
    const float* __restrict__ r1_w2, const float* __restrict__ r1_b2,
    const float* __restrict__ r1_w3, const float* __restrict__ r1_b3,
    const float* __restrict__ mix_l0, const float* __restrict__ mix_l1,
    const float* __restrict__ mix_l2)
{
    extern __shared__ float sm[];
    float* Xin = sm;            // 512
    float* Ysm = Xin + 512;     // 512 (mask premultiplied)
    float* mk  = Ysm + 512;     // 64
    float* Ha  = mk + 64;       // 4096
    float* Hb  = Ha + 4096;     // 4096
    float* Wb  = Hb + 4096;     // 4096
    float* G   = Wb + 4096;     // 576
    float* S   = G + 576;       // 16
    float* msg = S + 16;        // 1152
    float* t2  = msg + 1152;    // 128  -> 15248 floats (61KB)

    int t = threadIdx.x;
    int node = blockIdx.x;
    int pbase = node * 64;

    for (int idx = t; idx < 512; idx += 256) Xin[idx] = g_rad[(size_t)pbase*8 + idx];
    for (int idx = t; idx < 512; idx += 256)
        Ysm[idx] = g_Y[(size_t)pbase*8 + idx] * g_mask[pbase + (idx >> 3)];
    if (t < 64) mk[t] = g_mask[pbase + t];
    for (int idx = t; idx < 512; idx += 256) Wb[idx] = r1_w0[idx];
    __syncthreads();

    dl256<8>(Xin, Wb, r1_b0, Ha, t, 64);
    __syncthreads();
    for (int idx = t; idx < 4096; idx += 256) Wb[idx] = r1_w1[idx];
    __syncthreads();
    dl256<64>(Ha, Wb, r1_b1, Hb, t, 64);
    __syncthreads();
    for (int idx = t; idx < 4096; idx += 256) Wb[idx] = r1_w2[idx];
    __syncthreads();
    dl256<64>(Hb, Wb, r1_b2, Ha, t, 64);   // final H in Ha
    __syncthreads();

    // G[m][c] = sum_j maskY_m(j) * H[j][c]
    for (int idx = t; idx < 576; idx += 256) {
        int m = idx >> 6, c = idx & 63;
        float acc = 0.0f;
        #pragma unroll 8
        for (int j = 0; j < 64; ++j) {
            float yv = (m == 0) ? mk[j] : Ysm[j*8 + m - 1];
            acc += yv * Ha[j*64 + c];
        }
        G[idx] = acc;
    }
    if (t < 9) {
        float acc = 0.0f;
        for (int j = 0; j < 64; ++j) acc += (t == 0) ? mk[j] : Ysm[j*8 + t - 1];
        S[t] = acc;
    }
    __syncthreads();

    // msg[m][k] = (w_embed[k]/16)*(b3[o]*S[m] + sum_c G[m][c]*W3[c][o])
    {
        int k = t & 127;
        int g = t >> 7;
        float wk = w_embed[k] * 0.0625f;
        int mlo = g ? 4 : 0, mhi = g ? 9 : 4;
        #pragma unroll 1
        for (int m = mlo; m < mhi; ++m) {
            int o = k + ((m == 0) ? 0 : ((m <= 3) ? 128 : 256));
            float acc = r1_b3[o] * S[m];
            const float* Gm = G + m*64;
            #pragma unroll 8
            for (int c = 0; c < 64; ++c) acc += Gm[c] * r1_w3[c*384 + o];
            msg[m*128 + k] = acc * wk;
        }
    }
    __syncthreads();
    if (t < 128) {
        float a4 = msg[4*128+t], a5 = msg[5*128+t], a6 = msg[6*128+t],
              a7 = msg[7*128+t], a8 = msg[8*128+t];
        t2[t] = a4*a4 + a5*a5 + a6*a6 + a7*a7 + a8*a8;
    }
    __syncthreads();

    // tasks: 0 -> s1/h1, 1..3 -> v1[m]
    #pragma unroll
    for (int uu = 0; uu < 2; ++uu) {
        int u = t + uu*256;
        int task = u >> 7, k = u & 127;
        if (task == 0) {
            float s = 0.0f;
            #pragma unroll 4
            for (int c = 0; c < 128; ++c)
                s += msg[c]*mix_l0[c*128 + k] + t2[c]*mix_l2[c*128 + k];
            g_s1[node*128 + k] = s;
            g_h1[node*128 + k] = siluf(s);
        } else {
            float v = 0.0f;
            const float* mm = msg + task*128;
            #pragma unroll 4
            for (int c = 0; c < 128; ++c) v += mm[c]*mix_l1[c*128 + k];
            g_v1[(node*3 + (task-1))*128 + k] = v;
        }
    }
}

// ---------------- kernel 3: phase 2 (256 threads, E-GEMM form) ----------------
__global__ void __launch_bounds__(256) k_phase2(
    const float* __restrict__ r2_w0, const float* __restrict__ r2_b0,
    const float* __restrict__ r2_w1, const float* __restrict__ r2_b1,
    const float* __restrict__ r2_w2, const float* __restrict__ r2_b2,
    const float* __restrict__ r2_w3, const float* __restrict__ r2_b3,
    const float* __restrict__ mix2)
{
    extern __shared__ float sm[];
    float* Xin = sm;            // 512
    float* mk  = Xin + 512;     // 64
    float* Y1s = mk + 64;       // 192
    float* msA = Y1s + 192;     // 256
    float* msB = msA + 256;     // 256
    float* Wb  = msB + 256;     // 4096
    float* Ha  = Wb + 4096;     // 4352 (stride-68 H')
    float* E   = Ha + 4352;     // 8192 -> total 17920 floats (71.7KB)

    int t = threadIdx.x;
    int node = blockIdx.x;
    int b = node >> 6;
    int pbase = node * 64;

    for (int idx = t; idx < 512; idx += 256) Xin[idx] = g_rad[(size_t)pbase*8 + idx];
    if (t < 64) mk[t] = g_mask[pbase + t];
    if (t < 192) {
        int j = t / 3, m = t - j*3;
        Y1s[t] = g_Y[(size_t)pbase*8 + j*8 + m] * g_mask[pbase + j];
    }
    for (int idx = t; idx < 512; idx += 256) Wb[idx] = r2_w0[idx];
    __syncthreads();

    dl256<8>(Xin, Wb, r2_b0, E, t, 64);           // L0: -> E[0..4096)
    __syncthreads();
    for (int idx = t; idx < 4096; idx += 256) Wb[idx] = r2_w1[idx];
    __syncthreads();
    dl256<64>(E, Wb, r2_b1, E + 4096, t, 64);     // L1: -> E[4096..8192)
    __syncthreads();
    for (int idx = t; idx < 4096; idx += 256) Wb[idx] = r2_w2[idx];
    __syncthreads();
    dl256<64>(E + 4096, Wb, r2_b2, Ha, t, 68);    // L2: -> Ha stride 68
    __syncthreads();

    int j0 = (t >> 5) * 8;
    int k0 = (t & 31) * 4;
    int g  = t >> 7;          // 0/1 : j-half for dot
    int kk = t & 127;

    #pragma unroll 1
    for (int half = 0; half < 2; ++half) {
        int kb = half * 128;
        // E[j][k] = b3[kb+k] + sum_c H'[j][c] * W3[c][kb+k]   (FFMA2 GEMM)
        {
            u64 acc[8][2];
            u64 blo = pk2(r2_b3[kb+k0],   r2_b3[kb+k0+1]);
            u64 bhi = pk2(r2_b3[kb+k0+2], r2_b3[kb+k0+3]);
            #pragma unroll
            for (int r = 0; r < 8; ++r) { acc[r][0] = blo; acc[r][1] = bhi; }
            #pragma unroll 2
            for (int c = 0; c < 64; ++c) {
                longlong2 wq = *(const longlong2*)(r2_w3 + c*256 + kb + k0);
                #pragma unroll
                for (int r = 0; r < 8; ++r) {
                    float h = Ha[(j0+r)*68 + c];
                    u64 hp = pk2(h, h);
                    fma2(acc[r][0], hp, (u64)wq.x);
                    fma2(acc[r][1], hp, (u64)wq.y);
                }
            }
            #pragma unroll
            for (int r = 0; r < 8; ++r) {
                longlong2 st; st.x = (long long)acc[r][0]; st.y = (long long)acc[r][1];
                *(longlong2*)(E + (j0+r)*128 + k0) = st;
            }
        }
        __syncthreads();
        // dot: msg partial over j-half
        {
            float s = 0.0f;
            int jlo = g * 32;
            if (half == 0) {
                #pragma unroll 8
                for (int j = jlo; j < jlo + 32; ++j) {
                    float p = mk[j] * __ldg(g_h1 + (b*64 + j)*128 + kk);
                    s += p * E[j*128 + kk];
                }
                msA[g*128 + kk] = s;
            } else {
                #pragma unroll 8
                for (int j = jlo; j < jlo + 32; ++j) {
                    const float* vp = g_v1 + ((size_t)(b*64 + j)*3)*128 + kk;
                    float q = Y1s[j*3+0]*__ldg(vp) + Y1s[j*3+1]*__ldg(vp+128)
                            + Y1s[j*3+2]*__ldg(vp+256);
                    s += q * E[j*128 + kk];
                }
                msB[g*128 + kk] = s;
            }
        }
        __syncthreads();
    }

    if (t < 128) {
        msA[t] = (msA[t] + msA[128+t] + msB[t] + msB[128+t]) * 0.0625f;
    }
    __syncthreads();
    if (t < 128) {
        float s2v = 0.0f;
        #pragma unroll 4
        for (int c = 0; c < 128; ++c) s2v += msA[c] * mix2[c*128 + t];
        g_s2[node*128 + t] = s2v;
    }
}

// ---------------- kernel 4: final MLP (8 nodes/block, transposed, FFMA2) ----------------
__global__ void __launch_bounds__(512) k_mlp(
    const float* __restrict__ tim,
    const float* __restrict__ w0, const float* __restrict__ b0,
    const float* __restrict__ w1, const float* __restrict__ b1,
    const float* __restrict__ w2, const float* __restrict__ b2,
    float* __restrict__ out)
{
    extern __shared__ float sm[];
    float* xs_t  = sm;              // [641][8] = 5128
    float* h0s_t = xs_t + 5128;     // [512][8] = 4096
    float* h1s_t = xs_t;            // overlays xs_t after layer0

    int t = threadIdx.x;
    int rbase = blockIdx.x * 8;

    for (int idx = t; idx < 8*641; idx += 512) {
        int c = idx >> 3, r = idx & 7;
        int node = rbase + r;
        float v;
        if (c < 128)       v = g_s1[node*128 + c];
        else if (c < 512)  v = g_v1[(size_t)node*384 + (c - 128)];
        else if (c < 640)  v = g_s2[node*128 + (c - 512)];
        else               v = tim[node >> 6];
        xs_t[c*8 + r] = v;
    }
    __syncthreads();

    // layer 0: 641 -> 512, relu. thread t = output column, 8 rows packed.
    {
        u64 acc[4];
        u64 bb = pk2(b0[t], b0[t]);
        #pragma unroll
        for (int i = 0; i < 4; ++i) acc[i] = bb;
        #pragma unroll 4
        for (int c = 0; c < 641; ++c) {
            float w = __ldg(w0 + c*512 + t);
            u64 wp = pk2(w, w);
            const longlong2* xp = (const longlong2*)(xs_t + c*8);
            longlong2 qa = xp[0], qb = xp[1];
            fma2(acc[0], (u64)qa.x, wp); fma2(acc[1], (u64)qa.y, wp);
            fma2(acc[2], (u64)qb.x, wp); fma2(acc[3], (u64)qb.y, wp);
        }
        #pragma unroll
        for (int i = 0; i < 4; ++i) {
            float2 p = upk(acc[i]);
            h0s_t[t*8 + 2*i]     = fmaxf(p.x, 0.0f);
            h0s_t[t*8 + 2*i + 1] = fmaxf(p.y, 0.0f);
        }
    }
    __syncthreads();

    // layer 1: 512 -> 512, relu (writes h1s_t overlaying xs_t)
    {
        u64 acc[4];
        u64 bb = pk2(b1[t], b1[t]);
        #pragma unroll
        for (int i = 0; i < 4; ++i) acc[i] = bb;
        #pragma unroll 4
        for (int c = 0; c < 512; ++c) {
            float w = __ldg(w1 + c*512 + t);
            u64 wp = pk2(w, w);
            const longlong2* xp = (const longlong2*)(h0s_t + c*8);
            longlong2 qa = xp[0], qb = xp[1];
            fma2(acc[0], (u64)qa.x, wp); fma2(acc[1], (u64)qa.y, wp);
            fma2(acc[2], (u64)qb.x, wp); fma2(acc[3], (u64)qb.y, wp);
        }
        #pragma unroll
        for (int i = 0; i < 4; ++i) {
            float2 p = upk(acc[i]);
            h1s_t[t*8 + 2*i]     = fmaxf(p.x, 0.0f);
            h1s_t[t*8 + 2*i + 1] = fmaxf(p.y, 0.0f);
        }
    }
    __syncthreads();

    // layer 2: 512 -> 3 ; warp w (0..7) handles row r = w
    {
        int wid = t >> 5, lane = t & 31;
        if (wid < 8) {
            int r = wid;
            float p0 = 0.0f, p1 = 0.0f, p2 = 0.0f;
            for (int c = lane; c < 512; c += 32) {
                float hv = h1s_t[c*8 + r];
                p0 += hv * w2[c*3 + 0];
                p1 += hv * w2[c*3 + 1];
                p2 += hv * w2[c*3 + 2];
            }
            #pragma unroll
            for (int off = 16; off > 0; off >>= 1) {
                p0 += __shfl_down_sync(0xffffffffu, p0, off);
                p1 += __shfl_down_sync(0xffffffffu, p1, off);
                p2 += __shfl_down_sync(0xffffffffu, p2, off);
            }
            if (lane == 0) {
                int node = rbase + r;
                out[node*3 + 0] = p0 + b2[0];
                out[node*3 + 1] = p1 + b2[1];
                out[node*3 + 2] = p2 + b2[2];
            }
        }
    }
}

// ---------------- launch ----------------
extern "C" void kernel_launch(void* const* d_in, const int* in_sizes, int n_in,
                              void* d_out, int out_size)
{
    const float* frac    = (const float*)d_in[0];
    const float* tim     = (const float*)d_in[1];
    const float* cell    = (const float*)d_in[2];
    const float* w_embed = (const float*)d_in[3];
    const float* r1_w0 = (const float*)d_in[4];
    const float* r1_b0 = (const float*)d_in[5];
    const float* r1_w1 = (const float*)d_in[6];
    const float* r1_b1 = (const float*)d_in[7];
    const float* r1_w2 = (const float*)d_in[8];
    const float* r1_b2 = (const float*)d_in[9];
    const float* r1_w3 = (const float*)d_in[10];
    const float* r1_b3 = (const float*)d_in[11];
    const float* mix1_l0 = (const float*)d_in[12];
    const float* mix1_l1 = (const float*)d_in[13];
    const float* mix1_l2 = (const float*)d_in[14];
    const float* r2_w0 = (const float*)d_in[15];
    const float* r2_b0 = (const float*)d_in[16];
    const float* r2_w1 = (const float*)d_in[17];
    const float* r2_b1 = (const float*)d_in[18];
    const float* r2_w2 = (const float*)d_in[19];
    const float* r2_b2 = (const float*)d_in[20];
    const float* r2_w3 = (const float*)d_in[21];
    const float* r2_b3 = (const float*)d_in[22];
    const float* mix2  = (const float*)d_in[23];
    const float* mlp_w0 = (const float*)d_in[24];
    const float* mlp_b0 = (const float*)d_in[25];
    const float* mlp_w1 = (const float*)d_in[26];
    const float* mlp_b1 = (const float*)d_in[27];
    const float* mlp_w2 = (const float*)d_in[28];
    const float* mlp_b2 = (const float*)d_in[29];

    const int SM_P1  = 15248 * 4;
    const int SM_P2  = 17920 * 4;
    const int SM_MLP = (5128 + 4096) * 4;

    cudaFuncSetAttribute(k_phase1, cudaFuncAttributeMaxDynamicSharedMemorySize, SM_P1);
    cudaFuncSetAttribute(k_phase2, cudaFuncAttributeMaxDynamicSharedMemorySize, SM_P2);
    cudaFuncSetAttribute(k_mlp,    cudaFuncAttributeMaxDynamicSharedMemorySize, SM_MLP);

    k_geom<<<NPAIR/256, 256>>>(frac, cell);
    k_phase1<<<NNODE, 256, SM_P1>>>(w_embed,
        r1_w0, r1_b0, r1_w1, r1_b1, r1_w2, r1_b2, r1_w3, r1_b3,
        mix1_l0, mix1_l1, mix1_l2);
    k_phase2<<<NNODE, 256, SM_P2>>>(
        r2_w0, r2_b0, r2_w1, r2_b1, r2_w2, r2_b2, r2_w3, r2_b3, mix2);
    k_mlp<<<NNODE/8, 512, SM_MLP>>>(tim, mlp_w0, mlp_b0, mlp_w1, mlp_b1,
        mlp_w2, mlp_b2, (float*)d_out);
}